// round 3
// baseline (speedup 1.0000x reference)
#include <cuda_runtime.h>

// Problem constants
#define Bq   8
#define Cc   256
#define HWp  4096          // 64*64
#define Nn   1024
#define Dd   256
#define PIX  (Bq*HWp)      // 32768 pixels

// Tiling
#define TP   128           // pixels per block
#define TN   128           // n per chunk
#define KC   32            // c per k-stage
#define NCHUNK (Nn/TN)     // 8
#define KSTG   (Cc/KC)     // 8
#define WS   132           // w_s row stride (pad, 132*4=528B: 16B-aligned rows)
#define GS   257           // gather row stride (pad, conflict-free transpose)

// Output layout: [z_q (8*256*64*64) | diff (1) | ind (8*64*64)] as float32
#define ZQ_SIZE  (Bq*Dd*HWp)
#define DIFF_OFF ZQ_SIZE
#define IND_OFF  (ZQ_SIZE+1)

#define SMEM_FLOATS (Cc*TP + KC*WS)
#define SMEM_BYTES  (SMEM_FLOATS * 4)

extern __shared__ float sm_dyn[];

typedef unsigned long long u64;

// d.lo += a.lo*b.lo ; d.hi += a.hi*b.hi   (exact per-lane IEEE fp32 FMA)
__device__ __forceinline__ void ffma2(u64& d, u64 a, u64 b) {
    asm("fma.rn.f32x2 %0, %1, %2, %0;" : "+l"(d) : "l"(a), "l"(b));
}

__device__ __forceinline__ u64 swap2(u64 v) {
    float lo, hi;
    asm("mov.b64 {%0, %1}, %2;" : "=f"(lo), "=f"(hi) : "l"(v));
    u64 r;
    asm("mov.b64 %0, {%1, %2};" : "=l"(r) : "f"(hi), "f"(lo));
    return r;
}

__device__ __forceinline__ void unpack2(u64 v, float& lo, float& hi) {
    asm("mov.b64 {%0, %1}, %2;" : "=f"(lo), "=f"(hi) : "l"(v));
}

__global__ __launch_bounds__(256, 1)
void aq_kernel(const float* __restrict__ z,
               const float* __restrict__ pw,
               const float* __restrict__ pb,
               const float* __restrict__ emb,
               float* __restrict__ out)
{
    float* z_s = sm_dyn;            // [Cc][TP]  (c-major, matches z layout)
    float* w_s = sm_dyn + Cc * TP;  // [KC][WS]  (c-major, transposed on load)
    __shared__ int s_idx[TP];

    const int tid  = threadIdx.x;
    const int pix0 = blockIdx.x * TP;          // global pixel base
    const int b    = pix0 >> 12;               // /4096 (tile never crosses batch)
    const int hw0  = pix0 & (HWp - 1);
    const float* zb = z + (size_t)b * Cc * HWp + hw0;

    // ---- Load full z tile [256 c][128 p] into smem (coalesced, once) ----
    #pragma unroll
    for (int i = 0; i < 32; i++) {
        int e4 = tid + i * 256;                // 8192 float4s total
        int c  = e4 >> 5;                      // 32 float4 per c-row
        int p4 = (e4 & 31) << 2;
        float4 v = *(const float4*)(zb + (size_t)c * HWp + p4);
        *(float4*)(z_s + c * TP + p4) = v;
    }
    // (first __syncthreads inside k-loop orders these stores before compute)

    const int tx = tid & 15;   // n sub-tile (8 n's each)
    const int ty = tid >> 4;   // pixel row  (8 pixels each)

    float bestV[8];
    int   bestI[8];
    #pragma unroll
    for (int i = 0; i < 8; i++) { bestV[i] = -3.4e38f; bestI[i] = 0; }

    #pragma unroll 1
    for (int nc = 0; nc < NCHUNK; nc++) {
        const int nBase = nc * TN;
        // Packed accumulators covering 8x8 (pixel i x n j) via 2x2 blocks:
        // accD[k][m] = (acc[2k][2m]  , acc[2k+1][2m+1])   diagonal
        // accA[k][m] = (acc[2k][2m+1], acc[2k+1][2m]  )   anti-diagonal
        u64 accD[4][4], accA[4][4];
        #pragma unroll
        for (int k = 0; k < 4; k++)
            #pragma unroll
            for (int m = 0; m < 4; m++) { accD[k][m] = 0ull; accA[k][m] = 0ull; }

        #pragma unroll 1
        for (int ks = 0; ks < KSTG; ks++) {
            // ---- stage w chunk [128 n][32 c] -> w_s[c][n] (transposed) ----
            #pragma unroll
            for (int i = 0; i < 4; i++) {
                int e  = tid + i * 256;        // 1024 float4s
                int n  = e >> 3;               // 8 float4 per n-row
                int c4 = (e & 7) << 2;
                float4 v = *(const float4*)(pw + (size_t)(nBase + n) * Cc + ks * KC + c4);
                w_s[(c4 + 0) * WS + n] = v.x;
                w_s[(c4 + 1) * WS + n] = v.y;
                w_s[(c4 + 2) * WS + n] = v.z;
                w_s[(c4 + 3) * WS + n] = v.w;
            }
            __syncthreads();

            #pragma unroll
            for (int c = 0; c < KC; c++) {
                const float* zr = z_s + (ks * KC + c) * TP + ty * 8;
                const float* wr = w_s + c * WS + tx * 8;
                // 64-bit aligned pair loads (LDS.128 quads -> aligned reg pairs)
                ulonglong2 za = *(const ulonglong2*)zr;        // (z0,z1),(z2,z3)
                ulonglong2 zc = *(const ulonglong2*)(zr + 4);  // (z4,z5),(z6,z7)
                ulonglong2 wa = *(const ulonglong2*)wr;
                ulonglong2 wc = *(const ulonglong2*)(wr + 4);
                u64 zp[4] = {za.x, za.y, zc.x, zc.y};
                u64 wp[4] = {wa.x, wa.y, wc.x, wc.y};
                u64 ws4[4];
                #pragma unroll
                for (int m = 0; m < 4; m++) ws4[m] = swap2(wp[m]);

                #pragma unroll
                for (int k = 0; k < 4; k++)
                    #pragma unroll
                    for (int m = 0; m < 4; m++) {
                        ffma2(accD[k][m], zp[k], wp[m]);   // (i0*j0, i1*j1)
                        ffma2(accA[k][m], zp[k], ws4[m]);  // (i0*j1, i1*j0)
                    }
            }
            __syncthreads();
        }

        // ---- unpack packed accumulators into scalar 8x8 tile ----
        float acc[8][8];
        #pragma unroll
        for (int k = 0; k < 4; k++)
            #pragma unroll
            for (int m = 0; m < 4; m++) {
                unpack2(accD[k][m], acc[2*k][2*m],     acc[2*k+1][2*m+1]);
                unpack2(accA[k][m], acc[2*k][2*m+1],   acc[2*k+1][2*m]);
            }

        // ---- bias + fused argmax for this n-chunk ----
        float4 b0 = *(const float4*)(pb + nBase + tx * 8);
        float4 b1 = *(const float4*)(pb + nBase + tx * 8 + 4);
        float bias[8] = {b0.x, b0.y, b0.z, b0.w, b1.x, b1.y, b1.z, b1.w};

        #pragma unroll
        for (int i = 0; i < 8; i++) {
            float v  = acc[i][0] + bias[0];
            int  idx = nBase + tx * 8;
            #pragma unroll
            for (int j = 1; j < 8; j++) {
                float t = acc[i][j] + bias[j];
                if (t > v) { v = t; idx = nBase + tx * 8 + j; }   // strict >: keep earliest
            }
            // butterfly over the 16 tx lanes (never crosses half-warp: xor<=8)
            #pragma unroll
            for (int s = 1; s < 16; s <<= 1) {
                float ov = __shfl_xor_sync(0xffffffffu, v, s);
                int   oi = __shfl_xor_sync(0xffffffffu, idx, s);
                if (ov > v || (ov == v && oi < idx)) { v = ov; idx = oi; }
            }
            if (v > bestV[i] || (v == bestV[i] && idx < bestI[i])) {
                bestV[i] = v; bestI[i] = idx;
            }
        }
    }

    if (tx == 0) {
        #pragma unroll
        for (int i = 0; i < 8; i++) s_idx[ty * 8 + i] = bestI[i];
    }
    __syncthreads();

    // ---- write ind (as float) and diff ----
    if (tid < TP) out[IND_OFF + pix0 + tid] = (float)s_idx[tid];
    if (blockIdx.x == 0 && tid == 0) out[DIFF_OFF] = 0.0f;

    // ---- gather epilogue: z_q[b, d, hw] = embed[ind, d] ----
    // Phase A: coalesced row-gather embed[idx[p]][:] -> g_s[p][d] (pad 257)
    float* g_s = sm_dyn;   // reuse (z_s/w_s dead after sync above)
    #pragma unroll 4
    for (int it = 0; it < 32; it++) {
        int e4 = tid + it * 256;               // 8192 float4s
        int p  = e4 >> 6;                      // 64 float4 per row
        int d4 = (e4 & 63) << 2;
        float4 v = *(const float4*)(emb + (size_t)s_idx[p] * Dd + d4);
        g_s[p * GS + d4 + 0] = v.x;
        g_s[p * GS + d4 + 1] = v.y;
        g_s[p * GS + d4 + 2] = v.z;
        g_s[p * GS + d4 + 3] = v.w;
    }
    __syncthreads();
    // Phase B: transpose out of smem, coalesced [d][hw] stores
    float* outz = out + (size_t)b * Dd * HWp + hw0;
    #pragma unroll 8
    for (int it = 0; it < 128; it++) {
        int e = tid + it * 256;                // 32768 elements
        int d = e >> 7;
        int p = e & 127;
        outz[(size_t)d * HWp + p] = g_s[p * GS + d];  // banks (p+d)%32: conflict-free
    }
}

extern "C" void kernel_launch(void* const* d_in, const int* in_sizes, int n_in,
                              void* d_out, int out_size)
{
    const float* z   = (const float*)d_in[0];   // [8,256,64,64]
    const float* pw  = (const float*)d_in[1];   // [1024,256]
    const float* pb  = (const float*)d_in[2];   // [1024]
    const float* emb = (const float*)d_in[3];   // [1024,256]
    float* out = (float*)d_out;

    cudaFuncSetAttribute(aq_kernel, cudaFuncAttributeMaxDynamicSharedMemorySize, SMEM_BYTES);
    aq_kernel<<<PIX / TP, 256, SMEM_BYTES>>>(z, pw, pb, emb, out);
}

// round 6
// speedup vs baseline: 2.4878x; 2.4878x over previous
#include <cuda_runtime.h>
#include <cuda_fp16.h>
typedef unsigned int u32; typedef unsigned long long u64; typedef unsigned short u16;

#define HWp 4096
#define Cc  256
#define Dd  256
#define ZQ_SIZE (8*256*4096)
#define DIFF_OFF ZQ_SIZE
#define IND_OFF (ZQ_SIZE+1)

// ---- device scratch ----
// A frags: per tile t (128 px): hi 4096 uint4 + lo 4096 uint4 (128KB). [t][part][mt8][ks16][lane32]
__device__ uint4 g_Af[256*8192];
// B frags: per global stage gs (0..31, = chunk*4+stg): 32KB = 4096 u64. [gs][part][nt16][ksl4][lane32]
__device__ u64 g_Bf[32*4096];

__device__ __forceinline__ u32 smem_u32(const void* p){u32 a;asm("{ .reg .u64 t; cvta.to.shared.u64 t, %1; cvt.u32.u64 %0, t; }":"=r"(a):"l"(p));return a;}
__device__ __forceinline__ u32 ordu(float v){u32 u=__float_as_uint(v);return (u&0x80000000u)?~u:(u|0x80000000u);}
__device__ __forceinline__ void hmma(float* c,const u32* a,const u32* b){
  asm volatile("mma.sync.aligned.m16n8k16.row.col.f32.f16.f16.f32 {%0,%1,%2,%3}, {%4,%5,%6,%7}, {%8,%9}, {%0,%1,%2,%3};"
    : "+f"(c[0]),"+f"(c[1]),"+f"(c[2]),"+f"(c[3])
    : "r"(a[0]),"r"(a[1]),"r"(a[2]),"r"(a[3]),"r"(b[0]),"r"(b[1]));
}
__device__ __forceinline__ void cpa16(u32 dst,const void* src){
  asm volatile("cp.async.cg.shared.global [%0], [%1], 16;"::"r"(dst),"l"(src):"memory");
}
#define CPA_COMMIT() asm volatile("cp.async.commit_group;":::"memory")
#define CPA_WAIT1()  asm volatile("cp.async.wait_group 1;":::"memory")
#define CPA_WAIT0()  asm volatile("cp.async.wait_group 0;":::"memory")

__device__ __forceinline__ u16 h16(float v){__half h=__float2half_rn(v);return *(u16*)&h;}
__device__ __forceinline__ void splitH(float v,u16&h,u16&l){
  __half hb=__float2half_rn(v);
  float r=v-__half2float(hb);
  __half lb=__float2half_rn(r);
  h=*(u16*)&hb; l=*(u16*)&lb;
}

// ===================== K1: build fragment-major fp16 hi/lo operands =====================
extern __shared__ float k1s[];
__global__ __launch_bounds__(256,1) void k1(const float* __restrict__ z,const float* __restrict__ pw){
  int tid=threadIdx.x, t=blockIdx.x;
  if(t<256){
    // z tile t (pixels t*128..+127), scaled x64
    int pix0=t*128, b=pix0>>12, hw0=pix0&4095;
    const float* zb=z+(size_t)b*Cc*HWp+hw0;
    #pragma unroll
    for(int i=0;i<32;i++){
      int e4=tid+i*256; int c=e4>>5; int p4=(e4&31)<<2;
      float4 v=*(const float4*)(zb+(size_t)c*HWp+p4);
      float* d=k1s+c*129+p4;
      d[0]=v.x; d[1]=v.y; d[2]=v.z; d[3]=v.w;
    }
    __syncthreads();
    uint4* Ah=g_Af+(size_t)t*8192;
    uint4* Al=Ah+4096;
    #pragma unroll
    for(int i=0;i<16;i++){
      int u=tid+i*256;                 // [0,4096)
      int lane=u&31, ks=(u>>5)&15, mt=u>>9;
      int r0=mt*16+(lane>>2);
      int c0=ks*16+((lane&3)<<1);
      float v00=k1s[(c0  )*129+r0  ]*64.f, v01=k1s[(c0+1)*129+r0  ]*64.f;
      float v10=k1s[(c0  )*129+r0+8]*64.f, v11=k1s[(c0+1)*129+r0+8]*64.f;
      float v04=k1s[(c0+8)*129+r0  ]*64.f, v05=k1s[(c0+9)*129+r0  ]*64.f;
      float v14=k1s[(c0+8)*129+r0+8]*64.f, v15=k1s[(c0+9)*129+r0+8]*64.f;
      u16 h0,l0,h1,l1,h2,l2,h3,l3,h4,l4,h5,l5,h6,l6,h7,l7;
      splitH(v00,h0,l0); splitH(v01,h1,l1); splitH(v10,h2,l2); splitH(v11,h3,l3);
      splitH(v04,h4,l4); splitH(v05,h5,l5); splitH(v14,h6,l6); splitH(v15,h7,l7);
      uint4 H,L;
      H.x=h0|((u32)h1<<16); H.y=h2|((u32)h3<<16); H.z=h4|((u32)h5<<16); H.w=h6|((u32)h7<<16);
      L.x=l0|((u32)l1<<16); L.y=l2|((u32)l3<<16); L.z=l4|((u32)l5<<16); L.w=l6|((u32)l7<<16);
      Ah[u]=H; Al[u]=L;
    }
  } else {
    // pw frags, scaled x32: 32 CTAs x 2048 units (each unit = 4 (k,n) values, hi+lo u64)
    int base=(t-256)*2048;
    #pragma unroll
    for(int i=0;i<8;i++){
      int u=base+tid+i*256;            // [0,65536)
      int lane=u&31;
      int ksl=(u>>5)&3;
      int nt=(u>>7)&15;
      int stg=(u>>11)&3;
      int chunk=u>>13;                 // 0..7
      int n=chunk*128+nt*8+(lane>>2);
      int k0=(stg*4+ksl)*16+((lane&3)<<1);
      const float* sp=pw+(size_t)n*Cc;
      u16 h0,l0,h1,l1,h2,l2,h3,l3;
      splitH(sp[k0  ]*32.f,h0,l0);
      splitH(sp[k0+1]*32.f,h1,l1);
      splitH(sp[k0+8]*32.f,h2,l2);
      splitH(sp[k0+9]*32.f,h3,l3);
      u64 H=(u64)(h0|((u32)h1<<16)) | ((u64)(h2|((u32)h3<<16))<<32);
      u64 L=(u64)(l0|((u32)l1<<16)) | ((u64)(l2|((u32)l3<<16))<<32);
      int gs=chunk*4+stg;
      g_Bf[(size_t)gs*4096 + (nt*4+ksl)*32 + lane      ]=H;
      g_Bf[(size_t)gs*4096 + 2048 + (nt*4+ksl)*32 + lane]=L;
    }
  }
}

// ===================== K2: HMMA GEMM + fused argmax + gather =====================
// smem: A frags 128KB [0,131072) (hi 64KB, lo 64KB); B stages at 131072 + buf*32768
extern __shared__ char k2s[];
__global__ __launch_bounds__(256,1) void k2(const float* __restrict__ pb,const float* __restrict__ emb,float* __restrict__ out){
  __shared__ u64 s_best[128];
  __shared__ float s_pb[1024];
  __shared__ int s_idx[128];
  int tid=threadIdx.x, lane=tid&31, mw=(tid>>5)&3, nw=tid>>7, t=blockIdx.x;
  int pix0=t*128, b=pix0>>12, hw0=pix0&4095;
  char* sm=k2s;
  u32 smb=smem_u32(k2s);

  // load A tile frags (128KB) into smem
  {
    const uint4* src=g_Af+(size_t)t*8192;
    uint4* dst=(uint4*)sm;
    #pragma unroll
    for(int i=0;i<32;i++) dst[tid+i*256]=src[tid+i*256];
  }
  for(int i=tid;i<1024;i+=256) s_pb[i]=pb[i];
  if(tid<128) s_best[tid]=0ull;
  __syncthreads();

  // prologue: prefetch stages 0,1
  {
    u32 d0=smb+131072;
    const char* s0=(const char*)g_Bf;
    #pragma unroll
    for(int j2=0;j2<8;j2++){int e=tid+j2*256; cpa16(d0+e*16,s0+(size_t)e*16);}
    CPA_COMMIT();
    u32 d1=smb+131072+32768;
    const char* s1=(const char*)g_Bf+32768;
    #pragma unroll
    for(int j2=0;j2<8;j2++){int e=tid+j2*256; cpa16(d1+e*16,s1+(size_t)e*16);}
    CPA_COMMIT();
  }

  float bestV[4]; int bestI[4];
  #pragma unroll
  for(int i=0;i<4;i++){bestV[i]=-3.4e38f;bestI[i]=0;}
  const float inv=4.8828125e-4f;     // 1/2048

  const uint4* Ahp=(const uint4*)sm;
  const uint4* Alp=Ahp+4096;

  for(int nc=0;nc<8;nc++){
    float C[2][8][4];
    #pragma unroll
    for(int i=0;i<2;i++)
      #pragma unroll
      for(int j=0;j<8;j++)
        #pragma unroll
        for(int c=0;c<4;c++) C[i][j][c]=0.f;

    for(int stg=0;stg<4;stg++){
      int gs=nc*4+stg;
      CPA_WAIT1();
      __syncthreads();
      const char* Bst=sm+131072+(gs&1)*32768;
      #pragma unroll
      for(int ksl=0;ksl<4;ksl++){
        int ks=stg*4+ksl;
        u32 ah[2][4], al[2][4];
        #pragma unroll
        for(int i=0;i<2;i++){
          uint4 va=Ahp[((mw*2+i)*16+ks)*32+lane];
          ah[i][0]=va.x; ah[i][1]=va.y; ah[i][2]=va.z; ah[i][3]=va.w;
          uint4 vb=Alp[((mw*2+i)*16+ks)*32+lane];
          al[i][0]=vb.x; al[i][1]=vb.y; al[i][2]=vb.z; al[i][3]=vb.w;
        }
        u32 bh[8][2], bl[8][2];
        #pragma unroll
        for(int j=0;j<8;j++){
          int nt=nw*8+j;
          uint2 vh=*(const uint2*)(Bst+((nt*4+ksl)*32+lane)*8);
          uint2 vl=*(const uint2*)(Bst+16384+((nt*4+ksl)*32+lane)*8);
          bh[j][0]=vh.x; bh[j][1]=vh.y; bl[j][0]=vl.x; bl[j][1]=vl.y;
        }
        #pragma unroll
        for(int i=0;i<2;i++)
          #pragma unroll
          for(int j=0;j<8;j++){
            hmma(C[i][j],ah[i],bh[j]);
            hmma(C[i][j],ah[i],bl[j]);
            hmma(C[i][j],al[i],bh[j]);
          }
      }
      __syncthreads();
      // prefetch stage gs+2 into buf (gs&1)
      if(gs+2<32){
        u32 d=smb+131072+(gs&1)*32768;
        const char* s=(const char*)g_Bf+(size_t)(gs+2)*32768;
        #pragma unroll
        for(int j2=0;j2<8;j2++){int e=tid+j2*256; cpa16(d+e*16,s+(size_t)e*16);}
      }
      CPA_COMMIT();   // commit (possibly empty) group to keep wait_group bookkeeping uniform
    }

    // per-chunk bias + argmax
    int nb=nc*128+nw*64+((lane&3)<<1);
    #pragma unroll
    for(int i=0;i<2;i++){
      #pragma unroll
      for(int rr=0;rr<2;rr++){
        float v=-3.4e38f; int idx=0;
        #pragma unroll
        for(int j=0;j<8;j++){
          #pragma unroll
          for(int cc=0;cc<2;cc++){
            int n=nb+j*8+cc;
            float val=C[i][j][rr*2+cc]*inv+s_pb[n];
            if(val>v){v=val;idx=n;}
          }
        }
        #pragma unroll
        for(int s=1;s<4;s<<=1){
          float ov=__shfl_xor_sync(0xffffffffu,v,s);
          int   oi=__shfl_xor_sync(0xffffffffu,idx,s);
          if(ov>v||(ov==v&&oi<idx)){v=ov;idx=oi;}
        }
        int r=i*2+rr;
        if(v>bestV[r]||(v==bestV[r]&&idx<bestI[r])){bestV[r]=v;bestI[r]=idx;}
      }
    }
  }
  CPA_WAIT0();

  // merge across warps (2 n-warps share each pixel row)
  if((lane&3)==0){
    #pragma unroll
    for(int i=0;i<2;i++)
      #pragma unroll
      for(int rr=0;rr<2;rr++){
        int row=mw*32+i*16+rr*8+(lane>>2);
        u64 key=((u64)ordu(bestV[i*2+rr])<<32)|(u32)(1023-bestI[i*2+rr]);
        atomicMax(&s_best[row],key);
      }
  }
  __syncthreads();
  if(tid<128){
    int idx=1023-(int)(s_best[tid]&0xffffffffull);
    s_idx[tid]=idx;
    out[IND_OFF+pix0+tid]=(float)idx;
  }
  if(t==0&&tid==0) out[DIFF_OFF]=0.0f;
  __syncthreads();

  // gather epilogue: z_q[b,d,hw] = embed[ind,d]
  float* gs2=(float*)sm;      // [128][257] = 131584B, fits
  for(int i=tid;i<8192;i+=256){
    int p=i>>6; int d4=(i&63)<<2;
    float4 v=*(const float4*)(emb+(size_t)s_idx[p]*Dd+d4);
    float* d=gs2+p*257+d4;
    d[0]=v.x; d[1]=v.y; d[2]=v.z; d[3]=v.w;
  }
  __syncthreads();
  float* outz=out+(size_t)b*Dd*HWp+hw0;
  for(int i=tid;i<32768;i+=256){
    int d=i>>7, p=i&127;
    outz[(size_t)d*HWp+p]=gs2[p*257+d];
  }
}

extern "C" void kernel_launch(void* const* d_in, const int* in_sizes, int n_in,
                              void* d_out, int out_size)
{
  const float* z  =(const float*)d_in[0];
  const float* pw =(const float*)d_in[1];
  const float* pb =(const float*)d_in[2];
  const float* emb=(const float*)d_in[3];
  float* out=(float*)d_out;
  cudaFuncSetAttribute(k1,cudaFuncAttributeMaxDynamicSharedMemorySize,132096);
  cudaFuncSetAttribute(k2,cudaFuncAttributeMaxDynamicSharedMemorySize,196608);
  k1<<<288,256,132096>>>(z,pw);
  k2<<<256,256,196608>>>(pb,emb,out);
}

// round 7
// speedup vs baseline: 2.5831x; 1.0383x over previous
#include <cuda_runtime.h>
#include <cuda_fp16.h>
typedef unsigned int u32; typedef unsigned long long u64; typedef unsigned short u16;

#define HWp 4096
#define Cc  256
#define Dd  256
#define ZQ_SIZE (8*256*4096)
#define DIFF_OFF ZQ_SIZE
#define IND_OFF (ZQ_SIZE+1)

// ---- device scratch ----
// A frags: per tile t (128 px): hi 4096 uint4 + lo 4096 uint4 (128KB). [t][part][mt8][ks16][lane32]
__device__ uint4 g_Af[256*8192];
// B frags: per global stage gs (0..31): 32KB = 4096 u64. [gs][part][nt16][ksl4][lane32]
__device__ u64 g_Bf[32*4096];

__device__ __forceinline__ u32 smem_u32(const void* p){u32 a;asm("{ .reg .u64 t; cvta.to.shared.u64 t, %1; cvt.u32.u64 %0, t; }":"=r"(a):"l"(p));return a;}
__device__ __forceinline__ u32 ordu(float v){u32 u=__float_as_uint(v);return (u&0x80000000u)?~u:(u|0x80000000u);}
__device__ __forceinline__ void hmma(float* c,const u32* a,const u32* b){
  asm volatile("mma.sync.aligned.m16n8k16.row.col.f32.f16.f16.f32 {%0,%1,%2,%3}, {%4,%5,%6,%7}, {%8,%9}, {%0,%1,%2,%3};"
    : "+f"(c[0]),"+f"(c[1]),"+f"(c[2]),"+f"(c[3])
    : "r"(a[0]),"r"(a[1]),"r"(a[2]),"r"(a[3]),"r"(b[0]),"r"(b[1]));
}
__device__ __forceinline__ void cpa16(u32 dst,const void* src){
  asm volatile("cp.async.cg.shared.global [%0], [%1], 16;"::"r"(dst),"l"(src):"memory");
}
#define CPA_COMMIT() asm volatile("cp.async.commit_group;":::"memory")
#define CPA_WAIT1()  asm volatile("cp.async.wait_group 1;":::"memory")
#define CPA_WAIT0()  asm volatile("cp.async.wait_group 0;":::"memory")

__device__ __forceinline__ void splitH(float v,u16&h,u16&l){
  __half hb=__float2half_rn(v);
  float r=v-__half2float(hb);
  __half lb=__float2half_rn(r);
  h=*(u16*)&hb; l=*(u16*)&lb;
}

// ===================== K1: build fragment-major fp16 hi/lo operands =====================
extern __shared__ float k1s[];
__global__ __launch_bounds__(256,1) void k1(const float* __restrict__ z,const float* __restrict__ pw){
  int tid=threadIdx.x, t=blockIdx.x;
  if(t<256){
    // z tile t (pixels t*128..+127), scaled x64
    int pix0=t*128, b=pix0>>12, hw0=pix0&4095;
    const float* zb=z+(size_t)b*Cc*HWp+hw0;
    #pragma unroll
    for(int i=0;i<32;i++){
      int e4=tid+i*256; int c=e4>>5; int p4=(e4&31)<<2;
      float4 v=*(const float4*)(zb+(size_t)c*HWp+p4);
      float* d=k1s+c*129+p4;
      d[0]=v.x; d[1]=v.y; d[2]=v.z; d[3]=v.w;
    }
    __syncthreads();
    uint4* Ah=g_Af+(size_t)t*8192;
    uint4* Al=Ah+4096;
    #pragma unroll
    for(int i=0;i<16;i++){
      int u=tid+i*256;                 // [0,4096)
      int lane=u&31, ks=(u>>5)&15, mt=u>>9;
      int r0=mt*16+(lane>>2);
      int c0=ks*16+((lane&3)<<1);
      float v00=k1s[(c0  )*129+r0  ]*64.f, v01=k1s[(c0+1)*129+r0  ]*64.f;
      float v10=k1s[(c0  )*129+r0+8]*64.f, v11=k1s[(c0+1)*129+r0+8]*64.f;
      float v04=k1s[(c0+8)*129+r0  ]*64.f, v05=k1s[(c0+9)*129+r0  ]*64.f;
      float v14=k1s[(c0+8)*129+r0+8]*64.f, v15=k1s[(c0+9)*129+r0+8]*64.f;
      u16 h0,l0,h1,l1,h2,l2,h3,l3,h4,l4,h5,l5,h6,l6,h7,l7;
      splitH(v00,h0,l0); splitH(v01,h1,l1); splitH(v10,h2,l2); splitH(v11,h3,l3);
      splitH(v04,h4,l4); splitH(v05,h5,l5); splitH(v14,h6,l6); splitH(v15,h7,l7);
      uint4 H,L;
      H.x=h0|((u32)h1<<16); H.y=h2|((u32)h3<<16); H.z=h4|((u32)h5<<16); H.w=h6|((u32)h7<<16);
      L.x=l0|((u32)l1<<16); L.y=l2|((u32)l3<<16); L.z=l4|((u32)l5<<16); L.w=l6|((u32)l7<<16);
      Ah[u]=H; Al[u]=L;
    }
  } else {
    // pw frags, scaled x32
    int base=(t-256)*2048;
    #pragma unroll
    for(int i=0;i<8;i++){
      int u=base+tid+i*256;            // [0,65536)
      int lane=u&31;
      int ksl=(u>>5)&3;
      int nt=(u>>7)&15;
      int stg=(u>>11)&3;
      int chunk=u>>13;                 // 0..7
      int n=chunk*128+nt*8+(lane>>2);
      int k0=(stg*4+ksl)*16+((lane&3)<<1);
      const float* sp=pw+(size_t)n*Cc;
      u16 h0,l0,h1,l1,h2,l2,h3,l3;
      splitH(sp[k0  ]*32.f,h0,l0);
      splitH(sp[k0+1]*32.f,h1,l1);
      splitH(sp[k0+8]*32.f,h2,l2);
      splitH(sp[k0+9]*32.f,h3,l3);
      u64 H=(u64)(h0|((u32)h1<<16)) | ((u64)(h2|((u32)h3<<16))<<32);
      u64 L=(u64)(l0|((u32)l1<<16)) | ((u64)(l2|((u32)l3<<16))<<32);
      int gs=chunk*4+stg;
      g_Bf[(size_t)gs*4096 + (nt*4+ksl)*32 + lane      ]=H;
      g_Bf[(size_t)gs*4096 + 2048 + (nt*4+ksl)*32 + lane]=L;
    }
  }
}

// ===================== K2: HMMA GEMM + fused argmax + gather (512 thr, 16 warps) =====================
// smem: A frags 128KB [0,131072) (hi 64KB, lo 64KB); B stages at 131072 + buf*32768
extern __shared__ char k2s[];
__global__ __launch_bounds__(512,1) void k2(const float* __restrict__ pb,const float* __restrict__ emb,float* __restrict__ out){
  __shared__ u64 s_best[128];
  __shared__ float s_pb[1024];
  __shared__ int s_idx[128];
  int tid=threadIdx.x, lane=tid&31, warp=tid>>5, mw=warp&3, nw=warp>>2, t=blockIdx.x;
  int pix0=t*128, b=pix0>>12, hw0=pix0&4095;
  char* sm=k2s;
  u32 smb=smem_u32(k2s);

  // load A tile frags (128KB) into smem
  {
    const uint4* src=g_Af+(size_t)t*8192;
    uint4* dst=(uint4*)sm;
    #pragma unroll
    for(int i=0;i<16;i++) dst[tid+i*512]=src[tid+i*512];
  }
  for(int i=tid;i<1024;i+=512) s_pb[i]=pb[i];
  if(tid<128) s_best[tid]=0ull;
  __syncthreads();

  // prologue: prefetch stages 0,1 (each 2048 x 16B)
  {
    u32 d0=smb+131072;
    const char* s0=(const char*)g_Bf;
    #pragma unroll
    for(int j2=0;j2<4;j2++){int e=tid+j2*512; cpa16(d0+e*16,s0+(size_t)e*16);}
    CPA_COMMIT();
    u32 d1=smb+131072+32768;
    const char* s1=(const char*)g_Bf+32768;
    #pragma unroll
    for(int j2=0;j2<4;j2++){int e=tid+j2*512; cpa16(d1+e*16,s1+(size_t)e*16);}
    CPA_COMMIT();
  }

  float bestV[4]; int bestI[4];
  #pragma unroll
  for(int i=0;i<4;i++){bestV[i]=-3.4e38f;bestI[i]=0;}
  const float inv=4.8828125e-4f;     // 1/2048

  const uint4* Ahp=(const uint4*)sm;
  const uint4* Alp=Ahp+4096;

  for(int nc=0;nc<8;nc++){
    float C[2][4][4];
    #pragma unroll
    for(int i=0;i<2;i++)
      #pragma unroll
      for(int j=0;j<4;j++)
        #pragma unroll
        for(int c=0;c<4;c++) C[i][j][c]=0.f;

    for(int stg=0;stg<4;stg++){
      int gs=nc*4+stg;
      CPA_WAIT1();
      __syncthreads();
      const char* Bst=sm+131072+(gs&1)*32768;
      #pragma unroll
      for(int ksl=0;ksl<4;ksl++){
        int ks=stg*4+ksl;
        u32 ah[2][4], al[2][4];
        #pragma unroll
        for(int i=0;i<2;i++){
          uint4 va=Ahp[((mw*2+i)*16+ks)*32+lane];
          ah[i][0]=va.x; ah[i][1]=va.y; ah[i][2]=va.z; ah[i][3]=va.w;
          uint4 vb=Alp[((mw*2+i)*16+ks)*32+lane];
          al[i][0]=vb.x; al[i][1]=vb.y; al[i][2]=vb.z; al[i][3]=vb.w;
        }
        u32 bh[4][2], bl[4][2];
        #pragma unroll
        for(int j=0;j<4;j++){
          int nt=nw*4+j;
          uint2 vh=*(const uint2*)(Bst+((nt*4+ksl)*32+lane)*8);
          uint2 vl=*(const uint2*)(Bst+16384+((nt*4+ksl)*32+lane)*8);
          bh[j][0]=vh.x; bh[j][1]=vh.y; bl[j][0]=vl.x; bl[j][1]=vl.y;
        }
        #pragma unroll
        for(int i=0;i<2;i++)
          #pragma unroll
          for(int j=0;j<4;j++){
            hmma(C[i][j],ah[i],bh[j]);
            hmma(C[i][j],ah[i],bl[j]);
            hmma(C[i][j],al[i],bh[j]);
          }
      }
      __syncthreads();
      // prefetch stage gs+2 into buf (gs&1)
      if(gs+2<32){
        u32 d=smb+131072+(gs&1)*32768;
        const char* s=(const char*)g_Bf+(size_t)(gs+2)*32768;
        #pragma unroll
        for(int j2=0;j2<4;j2++){int e=tid+j2*512; cpa16(d+e*16,s+(size_t)e*16);}
      }
      CPA_COMMIT();
    }

    // per-chunk bias + argmax (warp nw covers n in [nc*128+nw*32, +32))
    int nb=nc*128+nw*32+((lane&3)<<1);
    #pragma unroll
    for(int i=0;i<2;i++){
      #pragma unroll
      for(int rr=0;rr<2;rr++){
        float v=-3.4e38f; int idx=0;
        #pragma unroll
        for(int j=0;j<4;j++){
          #pragma unroll
          for(int cc=0;cc<2;cc++){
            int n=nb+j*8+cc;
            float val=C[i][j][rr*2+cc]*inv+s_pb[n];
            if(val>v){v=val;idx=n;}
          }
        }
        #pragma unroll
        for(int s=1;s<4;s<<=1){
          float ov=__shfl_xor_sync(0xffffffffu,v,s);
          int   oi=__shfl_xor_sync(0xffffffffu,idx,s);
          if(ov>v||(ov==v&&oi<idx)){v=ov;idx=oi;}
        }
        int r=i*2+rr;
        if(v>bestV[r]||(v==bestV[r]&&idx<bestI[r])){bestV[r]=v;bestI[r]=idx;}
      }
    }
  }
  CPA_WAIT0();

  // merge across the 4 n-warps sharing each pixel row
  if((lane&3)==0){
    #pragma unroll
    for(int i=0;i<2;i++)
      #pragma unroll
      for(int rr=0;rr<2;rr++){
        int row=mw*32+i*16+rr*8+(lane>>2);
        u64 key=((u64)ordu(bestV[i*2+rr])<<32)|(u32)(1023-bestI[i*2+rr]);
        atomicMax(&s_best[row],key);
      }
  }
  __syncthreads();
  if(tid<128){
    int idx=1023-(int)(s_best[tid]&0xffffffffull);
    s_idx[tid]=idx;
    out[IND_OFF+pix0+tid]=(float)idx;
  }
  if(t==0&&tid==0) out[DIFF_OFF]=0.0f;
  __syncthreads();

  // gather epilogue: z_q[b,d,hw] = embed[ind,d]
  float* gs2=(float*)sm;      // [128][257] = 131584B, fits in A region+B0
  for(int i=tid;i<8192;i+=512){
    int p=i>>6; int d4=(i&63)<<2;
    float4 v=*(const float4*)(emb+(size_t)s_idx[p]*Dd+d4);
    float* d=gs2+p*257+d4;
    d[0]=v.x; d[1]=v.y; d[2]=v.z; d[3]=v.w;
  }
  __syncthreads();
  float* outz=out+(size_t)b*Dd*HWp+hw0;
  for(int i=tid;i<32768;i+=512){
    int d=i>>7, p=i&127;
    outz[(size_t)d*HWp+p]=gs2[p*257+d];
  }
}

extern "C" void kernel_launch(void* const* d_in, const int* in_sizes, int n_in,
                              void* d_out, int out_size)
{
  const float* z  =(const float*)d_in[0];
  const float* pw =(const float*)d_in[1];
  const float* pb =(const float*)d_in[2];
  const float* emb=(const float*)d_in[3];
  float* out=(float*)d_out;
  cudaFuncSetAttribute(k1,cudaFuncAttributeMaxDynamicSharedMemorySize,132096);
  cudaFuncSetAttribute(k2,cudaFuncAttributeMaxDynamicSharedMemorySize,196608);
  k1<<<288,256,132096>>>(z,pw);
  k2<<<256,512,196608>>>(pb,emb,out);
}

// round 8
// speedup vs baseline: 2.8339x; 1.0971x over previous
#include <cuda_runtime.h>
#include <cuda_fp16.h>
typedef unsigned int u32; typedef unsigned long long u64; typedef unsigned short u16;

#define HWp 4096
#define Cc  256
#define Dd  256
#define ZQ_SIZE (8*256*4096)
#define DIFF_OFF ZQ_SIZE
#define IND_OFF (ZQ_SIZE+1)
#define DELTA 0.05f

// ---- device scratch ----
__device__ uint4 g_Af[256*4096];   // A hi frags: per tile t: 4096 uint4 (64KB)
__device__ u64   g_Bh[8*8192];     // B hi frags: per chunk nc: 8192 u64 (64KB)
__device__ float g_zt[32768*256];  // fp32 z, pixel-major

__device__ __forceinline__ u32 smem_u32(const void* p){u32 a;asm("{ .reg .u64 t; cvta.to.shared.u64 t, %1; cvt.u32.u64 %0, t; }":"=r"(a):"l"(p));return a;}
__device__ __forceinline__ u32 ordu(float v){u32 u=__float_as_uint(v);return (u&0x80000000u)?~u:(u|0x80000000u);}
__device__ __forceinline__ float unord(u32 u){return (u&0x80000000u)?__uint_as_float(u^0x80000000u):__uint_as_float(~u);}
__device__ __forceinline__ void hmma(float* c,const u32* a,const u32* b){
  asm volatile("mma.sync.aligned.m16n8k16.row.col.f32.f16.f16.f32 {%0,%1,%2,%3}, {%4,%5,%6,%7}, {%8,%9}, {%0,%1,%2,%3};"
    : "+f"(c[0]),"+f"(c[1]),"+f"(c[2]),"+f"(c[3])
    : "r"(a[0]),"r"(a[1]),"r"(a[2]),"r"(a[3]),"r"(b[0]),"r"(b[1]));
}
__device__ __forceinline__ void cpa16(u32 dst,const void* src){
  asm volatile("cp.async.cg.shared.global [%0], [%1], 16;"::"r"(dst),"l"(src):"memory");
}
#define CPA_COMMIT() asm volatile("cp.async.commit_group;":::"memory")
#define CPA_WAIT1()  asm volatile("cp.async.wait_group 1;":::"memory")
#define CPA_WAIT0()  asm volatile("cp.async.wait_group 0;":::"memory")

__device__ __forceinline__ u16 h16(float v){__half h=__float2half_rn(v);return *(u16*)&h;}

// exact fp32 warp dot: zv[8] per lane vs pw row n; deterministic xor-tree reduce
__device__ __forceinline__ float wdot(const float* zv,const float* __restrict__ pw,int n){
  const float* wr=pw+(size_t)n*Cc+(threadIdx.x&31)*8;
  float4 w0=*(const float4*)wr, w1=*(const float4*)(wr+4);
  float s=zv[0]*w0.x;
  s=fmaf(zv[1],w0.y,s); s=fmaf(zv[2],w0.z,s); s=fmaf(zv[3],w0.w,s);
  s=fmaf(zv[4],w1.x,s); s=fmaf(zv[5],w1.y,s); s=fmaf(zv[6],w1.z,s); s=fmaf(zv[7],w1.w,s);
  #pragma unroll
  for(int o=16;o>=1;o>>=1) s+=__shfl_xor_sync(0xffffffffu,s,o);
  return s;
}

// ===================== K1 =====================
extern __shared__ float k1s[];
__global__ __launch_bounds__(256,1) void k1(const float* __restrict__ z,const float* __restrict__ pw){
  int tid=threadIdx.x, t=blockIdx.x;
  if(t<256){
    int pix0=t*128, b=pix0>>12, hw0=pix0&4095;
    const float* zb=z+(size_t)b*Cc*HWp+hw0;
    #pragma unroll
    for(int i=0;i<32;i++){
      int e4=tid+i*256; int c=e4>>5; int p4=(e4&31)<<2;
      float4 v=*(const float4*)(zb+(size_t)c*HWp+p4);
      float* d=k1s+c*129+p4;
      d[0]=v.x; d[1]=v.y; d[2]=v.z; d[3]=v.w;
    }
    __syncthreads();
    #pragma unroll 8
    for(int i=0;i<128;i++) g_zt[(size_t)(pix0+i)*Cc+tid]=k1s[tid*129+i];
    uint4* Ah=g_Af+(size_t)t*4096;
    #pragma unroll
    for(int i=0;i<16;i++){
      int u=tid+i*256;
      int lane=u&31, ks=(u>>5)&15, mt=u>>9;
      int r0=mt*16+(lane>>2);
      int c0=ks*16+((lane&3)<<1);
      u16 h0=h16(k1s[(c0  )*129+r0  ]*64.f), h1=h16(k1s[(c0+1)*129+r0  ]*64.f);
      u16 h2=h16(k1s[(c0  )*129+r0+8]*64.f), h3=h16(k1s[(c0+1)*129+r0+8]*64.f);
      u16 h4=h16(k1s[(c0+8)*129+r0  ]*64.f), h5=h16(k1s[(c0+9)*129+r0  ]*64.f);
      u16 h6=h16(k1s[(c0+8)*129+r0+8]*64.f), h7=h16(k1s[(c0+9)*129+r0+8]*64.f);
      uint4 H;
      H.x=h0|((u32)h1<<16); H.y=h2|((u32)h3<<16); H.z=h4|((u32)h5<<16); H.w=h6|((u32)h7<<16);
      Ah[u]=H;
    }
  } else {
    int base=(t-256)*2048;
    #pragma unroll
    for(int i=0;i<8;i++){
      int u=base+tid+i*256;
      int lane=u&31;
      int ks=(u>>5)&15;
      int nt=(u>>9)&15;
      int chunk=u>>13;
      int n=chunk*128+nt*8+(lane>>2);
      int k0=ks*16+((lane&3)<<1);
      const float* sp=pw+(size_t)n*Cc;
      u16 h0=h16(sp[k0  ]*32.f), h1=h16(sp[k0+1]*32.f);
      u16 h2=h16(sp[k0+8]*32.f), h3=h16(sp[k0+9]*32.f);
      g_Bh[(size_t)chunk*8192 + (nt*16+ks)*32 + lane]
        = (u64)(h0|((u32)h1<<16)) | ((u64)(h2|((u32)h3<<16))<<32);
    }
  }
}

// ===================== K2 =====================
extern __shared__ char k2s[];
__global__ __launch_bounds__(512,1) void k2(const float* __restrict__ pw,const float* __restrict__ pb,
                                            const float* __restrict__ emb,float* __restrict__ out){
  __shared__ u32 s_best[128];
  __shared__ float s_pb[1024];
  __shared__ int s_idx[128];
  __shared__ int s_cnt[128];
  __shared__ u32 s_cand[128][32];
  int tid=threadIdx.x, lane=tid&31, warp=tid>>5, mw=warp&3, nw=warp>>2, t=blockIdx.x;
  int pix0=t*128, b=pix0>>12, hw0=pix0&4095;
  char* sm=k2s;
  u32 smb=smem_u32(k2s);

  { const uint4* src=g_Af+(size_t)t*4096; uint4* dst=(uint4*)sm;
    #pragma unroll
    for(int i=0;i<8;i++) dst[tid+i*512]=src[tid+i*512]; }
  for(int i=tid;i<1024;i+=512) s_pb[i]=pb[i];
  if(tid<128){ s_best[tid]=0u; s_cnt[tid]=0; }
  __syncthreads();

  #pragma unroll
  for(int c2=0;c2<2;c2++){
    u32 d=smb+65536+c2*65536;
    const char* s=(const char*)g_Bh+(size_t)c2*65536;
    #pragma unroll
    for(int j2=0;j2<8;j2++){int e=tid+j2*512; cpa16(d+e*16,s+(size_t)e*16);}
    CPA_COMMIT();
  }

  float bestV[4], secV[4]; int bestI[4];
  #pragma unroll
  for(int i=0;i<4;i++){bestV[i]=-3.4e38f;secV[i]=-3.4e38f;bestI[i]=0;}
  const float inv=4.8828125e-4f;
  const uint4* Ahp=(const uint4*)sm;

  for(int nc=0;nc<8;nc++){
    CPA_WAIT1();
    __syncthreads();
    const char* Bst=sm+65536+(nc&1)*65536;
    float C[2][4][4];
    #pragma unroll
    for(int i=0;i<2;i++)
      #pragma unroll
      for(int j=0;j<4;j++)
        #pragma unroll
        for(int c=0;c<4;c++) C[i][j][c]=0.f;

    #pragma unroll
    for(int ks=0;ks<16;ks++){
      u32 ah[2][4];
      #pragma unroll
      for(int i=0;i<2;i++){
        uint4 va=Ahp[((mw*2+i)*16+ks)*32+lane];
        ah[i][0]=va.x; ah[i][1]=va.y; ah[i][2]=va.z; ah[i][3]=va.w;
      }
      u32 bh[4][2];
      #pragma unroll
      for(int j=0;j<4;j++){
        int nt=nw*4+j;
        uint2 vh=*(const uint2*)(Bst+(size_t)((nt*16+ks)*32+lane)*8);
        bh[j][0]=vh.x; bh[j][1]=vh.y;
      }
      #pragma unroll
      for(int i=0;i<2;i++)
        #pragma unroll
        for(int j=0;j<4;j++)
          hmma(C[i][j],ah[i],bh[j]);
    }

    int nb=nc*128+nw*32+((lane&3)<<1);
    #pragma unroll
    for(int i=0;i<2;i++)
      #pragma unroll
      for(int rr=0;rr<2;rr++){
        int r=i*2+rr;
        #pragma unroll
        for(int j=0;j<4;j++)
          #pragma unroll
          for(int cc=0;cc<2;cc++){
            int n=nb+j*8+cc;
            float val=C[i][j][rr*2+cc]*inv+s_pb[n];
            if(val>bestV[r]){secV[r]=bestV[r];bestV[r]=val;bestI[r]=n;}
            else if(val>secV[r]) secV[r]=val;
          }
      }
    __syncthreads();
    if(nc+2<8){
      u32 d=smb+65536+(nc&1)*65536;
      const char* s=(const char*)g_Bh+(size_t)(nc+2)*65536;
      #pragma unroll
      for(int j2=0;j2<8;j2++){int e=tid+j2*512; cpa16(d+e*16,s+(size_t)e*16);}
    }
    CPA_COMMIT();
  }
  CPA_WAIT0();

  #pragma unroll
  for(int i=0;i<2;i++)
    #pragma unroll
    for(int rr=0;rr<2;rr++){
      int row=mw*32+i*16+rr*8+(lane>>2);
      atomicMax(&s_best[row],ordu(bestV[i*2+rr]));
    }
  __syncthreads();

  #pragma unroll
  for(int i=0;i<2;i++)
    #pragma unroll
    for(int rr=0;rr<2;rr++){
      int r=i*2+rr;
      int row=mw*32+i*16+rr*8+(lane>>2);
      float thr=unord(s_best[row])-DELTA;
      if(bestV[r]>=thr){
        int slot=atomicAdd(&s_cnt[row],1);
        s_cand[row][slot]=(u32)bestI[r];
      }
      if(secV[r]>=thr){
        int slot=atomicAdd(&s_cnt[row],1);
        s_cand[row][slot]=0x8000u|((u32)nw<<2)|(u32)(lane&3);
      }
    }
  __syncthreads();

  // exact rescore: one warp per pixel
  for(int p=warp;p<128;p+=16){
    const float* zr=g_zt+(size_t)(pix0+p)*Cc+lane*8;
    float4 z0=*(const float4*)zr, z1=*(const float4*)(zr+4);
    float zv[8]={z0.x,z0.y,z0.z,z0.w,z1.x,z1.y,z1.z,z1.w};
    float bv=-3.4e38f; int bi=1024;
    int cnt=s_cnt[p];
    for(int e=0;e<cnt;e++){
      u32 ent=s_cand[p][e];
      if(ent<0x8000u){
        int n=(int)ent;
        float v=wdot(zv,pw,n)+s_pb[n];
        if(v>bv||(v==bv&&n<bi)){bv=v;bi=n;}
      }else{
        int nwm=(int)((ent>>2)&3), q=(int)(ent&3);
        for(int nc2=0;nc2<8;nc2++)
          for(int j=0;j<4;j++)
            #pragma unroll
            for(int cc=0;cc<2;cc++){
              int n=nc2*128+nwm*32+j*8+q*2+cc;
              float v=wdot(zv,pw,n)+s_pb[n];
              if(v>bv||(v==bv&&n<bi)){bv=v;bi=n;}
            }
      }
    }
    if(lane==0){ s_idx[p]=bi; out[IND_OFF+pix0+p]=(float)bi; }
  }
  if(t==0&&tid==0) out[DIFF_OFF]=0.0f;
  __syncthreads();

  // gather epilogue
  float* gs2=(float*)sm;           // [128][257] = 131584B < 196608
  for(int i=tid;i<8192;i+=512){
    int p=i>>6; int d4=(i&63)<<2;
    float4 v=*(const float4*)(emb+(size_t)s_idx[p]*Dd+d4);
    float* d=gs2+p*257+d4;
    d[0]=v.x; d[1]=v.y; d[2]=v.z; d[3]=v.w;
  }
  __syncthreads();
  float* outz=out+(size_t)b*Dd*HWp+hw0;
  for(int i=tid;i<32768;i+=512){
    int d=i>>7, p=i&127;
    outz[(size_t)d*HWp+p]=gs2[p*257+d];
  }
}

extern "C" void kernel_launch(void* const* d_in, const int* in_sizes, int n_in,
                              void* d_out, int out_size)
{
  const float* z  =(const float*)d_in[0];
  const float* pw =(const float*)d_in[1];
  const float* pb =(const float*)d_in[2];
  const float* emb=(const float*)d_in[3];
  float* out=(float*)d_out;
  cudaFuncSetAttribute(k1,cudaFuncAttributeMaxDynamicSharedMemorySize,132096);
  cudaFuncSetAttribute(k2,cudaFuncAttributeMaxDynamicSharedMemorySize,196608);
  k1<<<288,256,132096>>>(z,pw);
  k2<<<256,512,196608>>>(pw,pb,emb,out);
}